// round 1
// baseline (speedup 1.0000x reference)
#include <cuda_runtime.h>

// Problem constants (fixed by the reference).
#define BB 4
#define SS 2048
#define DD 16
#define HH 16
#define NPAIR (BB*HH)      // 64 (b,h) pairs
#define TQ 128             // queries per attention block
#define NT (SS/TQ)         // 16 query tiles per pair

// Scratch (device globals; no allocations allowed).
__device__ float  g_q [NPAIR*SS];      // q * log2(e), [pair][s]
__device__ float2 g_kv[NPAIR*SS];      // (k, v) interleaved, [pair][s]
__device__ float  g_o [BB*SS*DD];      // attention output, [b][s][h]

__device__ __forceinline__ float ex2f(float x) {
    float r;
    asm("ex2.approx.ftz.f32 %0, %1;" : "=f"(r) : "f"(x));
    return r;
}

// ---------------------------------------------------------------------------
// Kernel 1: qkv = x @ w_qkv + b_qkv, scattered into attention-friendly layout.
// One thread per (b,s) row. grid 64 x 128 threads.
// ---------------------------------------------------------------------------
__global__ void qkv_kernel(const float* __restrict__ x,
                           const float* __restrict__ w,     // [16, 48] row-major
                           const float* __restrict__ bqkv)  // [48]
{
    __shared__ float sw[16 * 48];
    __shared__ float sb[48];
    int tid = threadIdx.x;
    for (int i = tid; i < 16 * 48; i += blockDim.x) sw[i] = w[i];
    if (tid < 48) sb[tid] = bqkv[tid];
    __syncthreads();

    int row = blockIdx.x * blockDim.x + tid;   // 0..B*S-1
    const float4* xr = reinterpret_cast<const float4*>(x + row * DD);
    float4 x0 = xr[0], x1 = xr[1], x2 = xr[2], x3 = xr[3];
    float xv[16] = { x0.x, x0.y, x0.z, x0.w,
                     x1.x, x1.y, x1.z, x1.w,
                     x2.x, x2.y, x2.z, x2.w,
                     x3.x, x3.y, x3.z, x3.w };

    int b = row / SS, s = row % SS;

    #pragma unroll
    for (int c = 0; c < 48; ++c) {
        float acc = sb[c];
        #pragma unroll
        for (int d = 0; d < 16; ++d) acc = fmaf(xv[d], sw[d * 48 + c], acc);
        int h   = c & 15;
        int idx = (b * HH + h) * SS + s;
        if (c < 16)       g_q[idx]    = acc * 1.44269504088896340736f; // scale=1, fold log2(e)
        else if (c < 32)  g_kv[idx].x = acc;
        else              g_kv[idx].y = acc;
    }
}

// ---------------------------------------------------------------------------
// Kernel 2: causal scalar-head attention.
// Block = one (pair, query-tile); TQ=128 threads, one query each.
// Heavy tiles (largest prefix) get the lowest blockIdx for wave balance.
// ---------------------------------------------------------------------------
__global__ void attn_kernel()
{
    __shared__ float2 skv[SS];   // 16 KB: (k,v) prefix

    int bx   = blockIdx.x;
    int pair = bx & (NPAIR - 1);           // bx % 64
    int tile = NT - 1 - (bx >> 6);         // heavy-first
    int tile_start = tile * TQ;
    int tile_end   = tile_start + TQ;

    const float2* __restrict__ kvp = g_kv + pair * SS;
    for (int j = threadIdx.x; j < tile_end; j += TQ) skv[j] = kvp[j];
    __syncthreads();

    int   i  = tile_start + threadIdx.x;
    float qi = g_q[pair * SS + i];

    float den0 = 0.f, den1 = 0.f, num0 = 0.f, num1 = 0.f;
    int j = 0;
    // main loop: two independent chains; j, j+1 both <= i while j < i
    #pragma unroll 4
    for (; j < i; j += 2) {
        float2 a = skv[j];
        float2 c = skv[j + 1];
        float e0 = ex2f(qi * a.x);
        float e1 = ex2f(qi * c.x);
        den0 += e0;  num0 = fmaf(e0, a.y, num0);
        den1 += e1;  num1 = fmaf(e1, c.y, num1);
    }
    if (j == i) {  // diagonal element when i is even
        float2 a = skv[j];
        float e = ex2f(qi * a.x);
        den0 += e;  num0 = fmaf(e, a.y, num0);
    }

    int b = pair >> 4, h = pair & 15;
    g_o[(b * SS + i) * DD + h] = (num0 + num1) / (den0 + den1);
}

// ---------------------------------------------------------------------------
// Kernel 3: out = o @ w_out + b_out. One thread per (b,s) row.
// ---------------------------------------------------------------------------
__global__ void proj_kernel(const float* __restrict__ w,   // [16,16] row-major
                            const float* __restrict__ bo,  // [16]
                            float* __restrict__ out)
{
    __shared__ float sw[16 * 16];
    __shared__ float sb[16];
    int tid = threadIdx.x;
    for (int i = tid; i < 256; i += blockDim.x) sw[i] = w[i];
    if (tid < 16) sb[tid] = bo[tid];
    __syncthreads();

    int row = blockIdx.x * blockDim.x + tid;
    const float4* orow = reinterpret_cast<const float4*>(g_o + row * DD);
    float4 o0 = orow[0], o1 = orow[1], o2 = orow[2], o3 = orow[3];
    float ov[16] = { o0.x, o0.y, o0.z, o0.w,
                     o1.x, o1.y, o1.z, o1.w,
                     o2.x, o2.y, o2.z, o2.w,
                     o3.x, o3.y, o3.z, o3.w };

    float res[16];
    #pragma unroll
    for (int c = 0; c < 16; ++c) {
        float acc = sb[c];
        #pragma unroll
        for (int d = 0; d < 16; ++d) acc = fmaf(ov[d], sw[d * 16 + c], acc);
        res[c] = acc;
    }

    float4* orow_out = reinterpret_cast<float4*>(out + row * DD);
    orow_out[0] = make_float4(res[0],  res[1],  res[2],  res[3]);
    orow_out[1] = make_float4(res[4],  res[5],  res[6],  res[7]);
    orow_out[2] = make_float4(res[8],  res[9],  res[10], res[11]);
    orow_out[3] = make_float4(res[12], res[13], res[14], res[15]);
}

// ---------------------------------------------------------------------------
extern "C" void kernel_launch(void* const* d_in, const int* in_sizes, int n_in,
                              void* d_out, int out_size)
{
    const float* x     = (const float*)d_in[0];  // [4,2048,16]
    const float* w_qkv = (const float*)d_in[1];  // [16,48]
    const float* b_qkv = (const float*)d_in[2];  // [48]
    const float* w_out = (const float*)d_in[3];  // [16,16]
    const float* b_out = (const float*)d_in[4];  // [16]
    float* out = (float*)d_out;                  // [4,2048,16]

    qkv_kernel<<<(BB * SS) / 128, 128>>>(x, w_qkv, b_qkv);
    attn_kernel<<<NPAIR * NT, TQ>>>();
    proj_kernel<<<(BB * SS) / 128, 128>>>(w_out, b_out, out);
}